// round 10
// baseline (speedup 1.0000x reference)
#include <cuda_runtime.h>
#include <cuda_bf16.h>
#include <mma.h>
#include <math.h>

using namespace nvcuda;

// ---------------- problem constants ----------------
#define BSZ   64
#define HID   512
#define G3    1536
#define LEN   400
#define TOUT  100
#define VOC   50000
#define LMAX  400
#define MROWS (TOUT*BSZ)
#define NCB   782           // phase-C column blocks: ceil(50000/64)
#define KDIM  512
#define NB2   32            // persistent grid for recurrent kernels
#define TB2   384           // 12 warps

// ---------------- device scratch (static, allocation-free) ----------------
__device__ float g_encGx[(size_t)LEN*BSZ*G3];    // x-gates for encoder (raw, no bias)
__device__ float g_attnx[(size_t)TOUT*BSZ*LMAX]; // x-part of attn logits, incl attn_b
__device__ float g_combx[(size_t)TOUT*BSZ*HID];  // x-part of combine, incl comb_b
__device__ int   g_dectok[TOUT*BSZ];
__device__ float g_h[BSZ*HID];                   // current hidden (fp32)
__device__ __nv_bfloat16 g_hbf[BSZ*HID];         // current hidden (bf16 GEMM input)
__device__ __nv_bfloat16 g_cbf[BSZ*HID];         // combined input (bf16 GEMM input)
__device__ float g_enc0[BSZ*HID];
__device__ float g_enc0W[BSZ*HID];
__device__ __nv_bfloat16 g_H2bf[(size_t)MROWS*HID];
__device__ __nv_bfloat16 g_embbf[(size_t)VOC*HID];
__device__ __nv_bfloat16 g_Wobf[(size_t)VOC*HID];
__device__ __nv_bfloat16 g_Wihbf[(size_t)G3*HID];
__device__ __nv_bfloat16 g_Whhbf[(size_t)G3*HID];
__device__ __nv_bfloat16 g_dWihbf[(size_t)G3*HID];
__device__ __nv_bfloat16 g_dWhhbf[(size_t)G3*HID];
__device__ float g_pm[(size_t)MROWS*NCB];
__device__ float g_ps[(size_t)MROWS*NCB];
__device__ float g_tgtlog[MROWS];
__device__ float g_lossp[32];

// grid barrier state
__device__ unsigned g_barcnt;
__device__ unsigned g_bargen;

__device__ __forceinline__ float sigmf(float x) { return 1.0f / (1.0f + expf(-x)); }

__device__ __forceinline__ void gridbarN(unsigned &gen, unsigned nblk)
{
    __syncthreads();
    if (threadIdx.x == 0) {
        __threadfence();
        unsigned prev = atomicAdd(&g_barcnt, 1u);
        if (prev == nblk - 1u) {
            atomicExch(&g_barcnt, 0u);
            __threadfence();
            atomicAdd(&g_bargen, 1u);
        } else {
            volatile unsigned* vg = &g_bargen;
            while (*vg == gen) { __nanosleep(32); }
        }
        gen++;
    }
    __syncthreads();
}

// ---------------- conversions ----------------
__global__ void k_tobf(const float* __restrict__ s, __nv_bfloat16* __restrict__ d, int n)
{
    int i = (blockIdx.x * 256 + threadIdx.x) << 2;
    if (i < n) {
        float4 v = *(const float4*)(s + i);
        *(__nv_bfloat162*)(d + i)     = __floats2bfloat162_rn(v.x, v.y);
        *(__nv_bfloat162*)(d + i + 2) = __floats2bfloat162_rn(v.z, v.w);
    }
}

// 4 recurrent weight matrices in ONE launch (768 blocks each)
__global__ void k_tobfW(const float* __restrict__ s0, const float* __restrict__ s1,
                        const float* __restrict__ s2, const float* __restrict__ s3)
{
    int arr = blockIdx.x / 768;
    int i = ((blockIdx.x % 768) * 256 + threadIdx.x) << 2;
    const float* s = (arr == 0) ? s0 : (arr == 1) ? s1 : (arr == 2) ? s2 : s3;
    __nv_bfloat16* d = (arr == 0) ? g_Wihbf : (arr == 1) ? g_Whhbf : (arr == 2) ? g_dWihbf : g_dWhhbf;
    float4 v = *(const float4*)(s + i);
    *(__nv_bfloat162*)(d + i)     = __floats2bfloat162_rn(v.x, v.y);
    *(__nv_bfloat162*)(d + i + 2) = __floats2bfloat162_rn(v.z, v.w);
}

__global__ void k_init(const int* __restrict__ tgt)
{
    int i = blockIdx.x * 256 + threadIdx.x;
    if (i < BSZ*HID) {
        g_h[i] = 0.0f;
        g_hbf[i] = __float2bfloat16(0.0f);
    }
    if (i < TOUT*BSZ) {
        int t = i / BSZ, b = i % BSZ;
        g_dectok[i] = (t == 0) ? 1 : tgt[(t-1)*BSZ + b];
    }
}

// ================= bf16 WMMA GEMM, 128x64 block, K=512 (phases A & C) =================
// MODE 0: A row m = Abf[gidx[m]] (token gather), store raw C to Cout (no bias).
// MODE 1: A row m = Abf[m], fused bias + streaming logsumexp epilogue.
template<int MODE>
__global__ void __launch_bounds__(256)
k_wgemm(const __nv_bfloat16* __restrict__ Abf,
        const int* __restrict__ gidx,
        const __nv_bfloat16* __restrict__ Bbf,
        const float* __restrict__ bias,
        float* __restrict__ Cout, int ldC,
        const int* __restrict__ tgt,
        int Ncols)
{
    __shared__ __align__(16) char sbuf[128*72*4];
    float* sC = (float*)sbuf;

    const int tid  = threadIdx.x;
    const int warp = tid >> 5;
    const int wm = warp >> 1;
    const int wn = warp & 1;
    const int bm = blockIdx.y * 128;
    const int bn = blockIdx.x * 64;

    const int cr = tid >> 2;
    const int ck = (tid & 3) << 3;

    size_t aoff0, aoff1;
    if (MODE == 0) {
        aoff0 = (size_t)gidx[bm + cr]      * KDIM + ck;
        aoff1 = (size_t)gidx[bm + cr + 64] * KDIM + ck;
    } else {
        aoff0 = (size_t)(bm + cr)      * KDIM + ck;
        aoff1 = (size_t)(bm + cr + 64) * KDIM + ck;
    }
    int nbr = bn + cr;
    if (nbr >= Ncols) nbr = Ncols - 1;
    size_t boff = (size_t)nbr * KDIM + ck;

    const int sa0 = cr*40 + ck;
    const int sa1 = (cr + 64)*40 + ck;

    __nv_bfloat16* sAb0 = (__nv_bfloat16*)sbuf;
    __nv_bfloat16* sBb0 = (__nv_bfloat16*)(sbuf + 10240);
    __nv_bfloat16* sAb1 = (__nv_bfloat16*)(sbuf + 15360);
    __nv_bfloat16* sBb1 = (__nv_bfloat16*)(sbuf + 25600);

    uint4 ra0 = *(const uint4*)(Abf + aoff0);
    uint4 ra1 = *(const uint4*)(Abf + aoff1);
    uint4 rb  = *(const uint4*)(Bbf + boff);
    *(uint4*)(sAb0 + sa0) = ra0;
    *(uint4*)(sAb0 + sa1) = ra1;
    *(uint4*)(sBb0 + sa0) = rb;
    __syncthreads();

    wmma::fragment<wmma::accumulator, 16, 16, 16, float> fc[2][2];
    for (int mi = 0; mi < 2; mi++)
        for (int ni = 0; ni < 2; ni++)
            wmma::fill_fragment(fc[mi][ni], 0.0f);

    for (int it = 0; it < 16; it++) {
        if (it < 15) {
            int kg = (it + 1) * 32;
            ra0 = *(const uint4*)(Abf + aoff0 + kg);
            ra1 = *(const uint4*)(Abf + aoff1 + kg);
            rb  = *(const uint4*)(Bbf + boff + kg);
        }
        __nv_bfloat16* cA = (it & 1) ? sAb1 : sAb0;
        __nv_bfloat16* cB = (it & 1) ? sBb1 : sBb0;
        for (int kk = 0; kk < 32; kk += 16) {
            wmma::fragment<wmma::matrix_a, 16, 16, 16, __nv_bfloat16, wmma::row_major> fa[2];
            wmma::fragment<wmma::matrix_b, 16, 16, 16, __nv_bfloat16, wmma::col_major> fb[2];
            wmma::load_matrix_sync(fa[0], cA + (wm*32     )*40 + kk, 40);
            wmma::load_matrix_sync(fa[1], cA + (wm*32 + 16)*40 + kk, 40);
            wmma::load_matrix_sync(fb[0], cB + (wn*32     )*40 + kk, 40);
            wmma::load_matrix_sync(fb[1], cB + (wn*32 + 16)*40 + kk, 40);
            for (int mi = 0; mi < 2; mi++)
                for (int ni = 0; ni < 2; ni++)
                    wmma::mma_sync(fc[mi][ni], fa[mi], fb[ni], fc[mi][ni]);
        }
        if (it < 15) {
            __nv_bfloat16* nA = (it & 1) ? sAb0 : sAb1;
            __nv_bfloat16* nB = (it & 1) ? sBb0 : sBb1;
            *(uint4*)(nA + sa0) = ra0;
            *(uint4*)(nA + sa1) = ra1;
            *(uint4*)(nB + sa0) = rb;
        }
        __syncthreads();
    }

    if (MODE == 0) {
        for (int mi = 0; mi < 2; mi++)
            for (int ni = 0; ni < 2; ni++) {
                size_t row = bm + wm*32 + mi*16;
                int col = bn + wn*32 + ni*16;
                wmma::store_matrix_sync(Cout + row * (size_t)ldC + col,
                                        fc[mi][ni], ldC, wmma::mem_row_major);
            }
    } else {
        for (int mi = 0; mi < 2; mi++)
            for (int ni = 0; ni < 2; ni++)
                wmma::store_matrix_sync(sC + (wm*32 + mi*16)*72 + wn*32 + ni*16,
                                        fc[mi][ni], 72, wmma::mem_row_major);
        __syncthreads();

        int r  = tid >> 1;
        int hf = tid & 1;
        float* crow = sC + r*72 + hf*32;
        float mx = -1e30f;
        for (int c = 0; c < 32; c++) {
            int gc = bn + hf*32 + c;
            float v = (gc < Ncols) ? (crow[c] + bias[gc]) : -1e30f;
            crow[c] = v;
            mx = fmaxf(mx, v);
        }
        float s = 0.0f;
        for (int c = 0; c < 32; c++) s += expf(crow[c] - mx);

        float mo = __shfl_xor_sync(0xffffffffu, mx, 1);
        float so = __shfl_xor_sync(0xffffffffu, s,  1);
        float M = fmaxf(mx, mo);
        float S = s * expf(mx - M) + so * expf(mo - M);

        int rg = bm + r;
        int tv = tgt[rg];
        int lc = tv - bn - hf*32;
        if (lc >= 0 && lc < 32) g_tgtlog[rg] = crow[lc];
        if (hf == 0) {
            g_pm[(size_t)rg * NCB + blockIdx.x] = M;
            g_ps[(size_t)rg * NCB + blockIdx.x] = S;
        }
    }
}

// ---------------- generic fp32 SGEMM (small phase-A ops) ----------------
template<bool GATHER>
__global__ void __launch_bounds__(256)
k_sgemm128(const float* __restrict__ A,
           const int*  __restrict__ gidx,
           const float* __restrict__ Bw, int ldb,
           const float* __restrict__ bias,
           float* __restrict__ C,
           int M, int N, int K)
{
    __shared__ __align__(16) float sA[16][128];
    __shared__ __align__(16) float sB[16][128];
    const int tid = threadIdx.x;
    const int bm = blockIdx.y * 128;
    const int bn = blockIdx.x * 128;
    const int tx = tid & 15;
    const int ty = tid >> 4;
    const int lr = tid >> 2;
    const int lk = (tid & 3) << 2;

    int m0 = bm + lr, m1 = m0 + 64;
    const bool mv0 = m0 < M, mv1 = m1 < M;
    size_t ar0, ar1;
    if (GATHER) {
        ar0 = (size_t)(mv0 ? gidx[m0] : gidx[0]) * (size_t)K;
        ar1 = (size_t)(mv1 ? gidx[m1] : gidx[0]) * (size_t)K;
    } else {
        ar0 = (size_t)(mv0 ? m0 : 0) * (size_t)K;
        ar1 = (size_t)(mv1 ? m1 : 0) * (size_t)K;
    }
    int n0 = bn + lr, n1 = n0 + 64;
    size_t br0 = (size_t)(n0 < N ? n0 : 0) * (size_t)ldb;
    size_t br1 = (size_t)(n1 < N ? n1 : 0) * (size_t)ldb;

    float acc[8][8];
#pragma unroll
    for (int i = 0; i < 8; i++)
#pragma unroll
        for (int j = 0; j < 8; j++) acc[i][j] = 0.0f;

    for (int kb = 0; kb < K; kb += 16) {
        float4 a0 = *(const float4*)(A  + ar0 + kb + lk);
        float4 a1 = *(const float4*)(A  + ar1 + kb + lk);
        float4 b0 = *(const float4*)(Bw + br0 + kb + lk);
        float4 b1 = *(const float4*)(Bw + br1 + kb + lk);
        __syncthreads();
        sA[lk+0][lr] = a0.x; sA[lk+1][lr] = a0.y; sA[lk+2][lr] = a0.z; sA[lk+3][lr] = a0.w;
        sA[lk+0][lr+64] = a1.x; sA[lk+1][lr+64] = a1.y; sA[lk+2][lr+64] = a1.z; sA[lk+3][lr+64] = a1.w;
        sB[lk+0][lr] = b0.x; sB[lk+1][lr] = b0.y; sB[lk+2][lr] = b0.z; sB[lk+3][lr] = b0.w;
        sB[lk+0][lr+64] = b1.x; sB[lk+1][lr+64] = b1.y; sB[lk+2][lr+64] = b1.z; sB[lk+3][lr+64] = b1.w;
        __syncthreads();
#pragma unroll
        for (int k = 0; k < 16; k++) {
            float4 pa0 = *(const float4*)(&sA[k][ty*8]);
            float4 pa1 = *(const float4*)(&sA[k][ty*8+4]);
            float4 pb0 = *(const float4*)(&sB[k][tx*8]);
            float4 pb1 = *(const float4*)(&sB[k][tx*8+4]);
            float av[8] = {pa0.x, pa0.y, pa0.z, pa0.w, pa1.x, pa1.y, pa1.z, pa1.w};
            float bv[8] = {pb0.x, pb0.y, pb0.z, pb0.w, pb1.x, pb1.y, pb1.z, pb1.w};
#pragma unroll
            for (int i = 0; i < 8; i++)
#pragma unroll
                for (int j = 0; j < 8; j++)
                    acc[i][j] += av[i] * bv[j];
        }
    }

#pragma unroll
    for (int i = 0; i < 8; i++) {
        int m = bm + ty*8 + i;
        if (m < M) {
            float* crow = C + (size_t)m * (size_t)N;
#pragma unroll
            for (int j = 0; j < 8; j++) {
                int n = bn + tx*8 + j;
                if (n < N) crow[n] = acc[i][j] + (bias ? bias[n] : 0.0f);
            }
        }
    }
}

// ---------------- staging maps for the persistent step-GEMMs ----------------
// encoder chunk: 448 uint4 tasks: [0,256) A = g_hbf (64 rows x 32 K), [256,448) B = Whh slice (48 rows)
__device__ __forceinline__ const __nv_bfloat16* enc_src(int s, int nc0, int k0)
{
    if (s < 256) { int row = s >> 2, q = s & 3; return g_hbf + row*HID + k0 + q*8; }
    int s2 = s - 256; int brow = s2 >> 2, q = s2 & 3;
    int grow = (brow >> 4)*HID + nc0 + (brow & 15);
    return g_Whhbf + (size_t)grow*HID + k0 + q*8;
}
__device__ __forceinline__ __nv_bfloat16* enc_dst(int s, char* buf)
{
    if (s < 256) { int row = s >> 2, q = s & 3; return (__nv_bfloat16*)buf + row*40 + q*8; }
    int s2 = s - 256; int brow = s2 >> 2, q = s2 & 3;
    return (__nv_bfloat16*)(buf + 5120) + brow*40 + q*8;
}
// decoder chunk: 896 tasks: [0,256) Ac = g_cbf, [256,512) Ah = g_hbf, [512,896) B (48 Wih + 48 Whh rows)
__device__ __forceinline__ const __nv_bfloat16* dec_src(int s, int nc0, int k0)
{
    if (s < 256) { int row = s >> 2, q = s & 3; return g_cbf + row*HID + k0 + q*8; }
    if (s < 512) { int s2 = s - 256; int row = s2 >> 2, q = s2 & 3; return g_hbf + row*HID + k0 + q*8; }
    int s2 = s - 512; int brow = s2 >> 2, q = s2 & 3;
    const __nv_bfloat16* W = (brow < 48) ? g_dWihbf : g_dWhhbf;
    int br = (brow < 48) ? brow : brow - 48;
    int grow = (br >> 4)*HID + nc0 + (br & 15);
    return W + (size_t)grow*HID + k0 + q*8;
}
__device__ __forceinline__ __nv_bfloat16* dec_dst(int s, char* buf)
{
    if (s < 256) { int row = s >> 2, q = s & 3; return (__nv_bfloat16*)buf + row*40 + q*8; }
    if (s < 512) { int s2 = s - 256; int row = s2 >> 2, q = s2 & 3; return (__nv_bfloat16*)(buf + 5120) + row*40 + q*8; }
    int s2 = s - 512; int brow = s2 >> 2, q = s2 & 3;
    return (__nv_bfloat16*)(buf + 10240) + brow*40 + q*8;
}

// ---------------- persistent encoder: 32 blocks, 1 grid barrier per step ----------------
__global__ void __launch_bounds__(TB2)
k_encoder(const float* __restrict__ bih, const float* __restrict__ bhh)
{
    __shared__ __align__(16) char sbuf[17920 + 13312];   // 2 x 8960 staging + sC 64x52 f32
    char* stg = sbuf;
    float* sC = (float*)(sbuf + 17920);

    const int tid  = threadIdx.x;
    const int warp = tid >> 5;
    const int rt   = warp & 3;        // row tile (16 rows of batch)
    const int gate = warp >> 2;       // 0..2
    const int nc0  = blockIdx.x * 16; // this block's h-column base

    unsigned gen = 0;
    if (tid == 0) gen = atomicAdd(&g_bargen, 0u);

    for (int t = 0; t < LEN; t++) {
        // stage chunk 0
        for (int s = tid; s < 448; s += TB2)
            *(uint4*)enc_dst(s, stg) = *(const uint4*)enc_src(s, nc0, 0);
        __syncthreads();

        wmma::fragment<wmma::accumulator,16,16,16,float> fc;
        wmma::fill_fragment(fc, 0.0f);

        for (int kc = 0; kc < 16; kc++) {
            uint4 r0; uint4 r1; bool h1 = false;
            if (kc < 15) {
                int k0n = (kc + 1) * 32;
                r0 = *(const uint4*)enc_src(tid, nc0, k0n);
                if (tid + TB2 < 448) { h1 = true; r1 = *(const uint4*)enc_src(tid + TB2, nc0, k0n); }
            }
            char* cbuf = stg + (kc & 1) * 8960;
            __nv_bfloat16* cA = (__nv_bfloat16*)cbuf;
            __nv_bfloat16* cB = (__nv_bfloat16*)(cbuf + 5120);
            for (int kk = 0; kk < 32; kk += 16) {
                wmma::fragment<wmma::matrix_a,16,16,16,__nv_bfloat16,wmma::row_major> fa;
                wmma::fragment<wmma::matrix_b,16,16,16,__nv_bfloat16,wmma::col_major> fb;
                wmma::load_matrix_sync(fa, cA + (rt*16)*40 + kk, 40);
                wmma::load_matrix_sync(fb, cB + (gate*16)*40 + kk, 40);
                wmma::mma_sync(fc, fa, fb, fc);
            }
            if (kc < 15) {
                char* nbuf = stg + ((kc + 1) & 1) * 8960;
                *(uint4*)enc_dst(tid, nbuf) = r0;
                if (h1) *(uint4*)enc_dst(tid + TB2, nbuf) = r1;
            }
            __syncthreads();
        }

        wmma::store_matrix_sync(sC + (rt*16)*52 + gate*16, fc, 52, wmma::mem_row_major);
        __syncthreads();

        // block-local gate fuse: 64 batches x 16 h-columns
        for (int idx = tid; idx < 1024; idx += TB2) {
            int b = idx >> 4, l = idx & 15;
            int j = nc0 + l;
            const float* gx = g_encGx + ((size_t)t*BSZ + b)*G3 + j;
            float hr = sC[b*52 + l]       + bhh[j];
            float hz = sC[b*52 + 16 + l]  + bhh[j+512];
            float hn = sC[b*52 + 32 + l]  + bhh[j+1024];
            float r = sigmf(gx[0]    + bih[j]      + hr);
            float z = sigmf(gx[512]  + bih[j+512]  + hz);
            float n = tanhf(gx[1024] + bih[j+1024] + r * hn);
            float hp = g_h[b*HID + j];
            float h2 = (1.0f - z)*n + z*hp;
            g_h[b*HID + j] = h2;
            g_hbf[b*HID + j] = __float2bfloat16(h2);
            if (t == 0) g_enc0[b*HID + j] = h2;
        }
        gridbarN(gen, NB2);
    }
}

// ---------------- persistent decoder: 32 blocks, 2 grid barriers per step ----------------
__global__ void __launch_bounds__(TB2)
k_decoder(const float* __restrict__ attn_W,
          const float* __restrict__ bih, const float* __restrict__ bhh)
{
    __shared__ __align__(16) char sbuf[35840];   // staging 2 x 17920; unioned with attn arrays / sC 64x100
    const int tid  = threadIdx.x;
    const int warp = tid >> 5;
    const int rt   = warp & 3;
    const int gate = warp >> 2;       // 0..2
    const int blk  = blockIdx.x;
    const int nc0  = blk * 16;

    unsigned gen = 0;
    if (tid == 0) gen = atomicAdd(&g_bargen, 0u);

    for (int t = 0; t < TOUT; t++) {
        // ---- P1: attention + cfuse (blocks 0..15, 4 batches each) ----
        if (blk < 16) {
            float* sh  = (float*)sbuf;                   // 4 x 512 f32
            float* slg = (float*)(sbuf + 8192);          // 4 x 400 f32
            float* srd = (float*)(sbuf + 14592);         // 384 f32
            float* sa0 = (float*)(sbuf + 16128);         // 4 f32
            int b0 = blk * 4;
            for (int i = tid; i < 2048; i += TB2) sh[i] = g_h[b0*HID + i];
            __syncthreads();
            for (int id = tid; id < 1600; id += TB2) {
                int bi = id & 3, l = id >> 2;
                const float4* w4 = (const float4*)(attn_W + (size_t)l*1024 + 512);
                const float4* h4 = (const float4*)(sh + bi*512);
                float s = 0.0f;
#pragma unroll 4
                for (int k = 0; k < 128; k++) {
                    float4 w = w4[k], h = h4[k];
                    s += w.x*h.x + w.y*h.y + w.z*h.z + w.w*h.w;
                }
                slg[bi*400 + l] = g_attnx[((size_t)t*BSZ + (b0+bi))*LMAX + l] + s;
            }
            __syncthreads();
            {
                int bi = tid & 3, u = tid >> 2;
                float p = 0.0f;
                for (int l = u; l < 400; l += 96) p += expf(slg[bi*400 + l]);
                srd[tid] = p;
                __syncthreads();
                if (tid < 192) srd[tid] += srd[tid + 192];
                __syncthreads();
                if (tid < 96)  srd[tid] += srd[tid + 96];
                __syncthreads();
                if (tid < 48)  srd[tid] += srd[tid + 48];
                __syncthreads();
                if (tid < 24)  srd[tid] += srd[tid + 24];
                __syncthreads();
                if (tid < 12)  srd[tid] += srd[tid + 12];
                __syncthreads();
                if (tid < 4)   sa0[tid] = expf(slg[tid*400]) / (srd[tid] + srd[tid+4] + srd[tid+8]);
                __syncthreads();
            }
            for (int i = tid; i < 2048; i += TB2) {
                int bi = i >> 9, j = i & 511;
                int b = b0 + bi;
                float v = g_combx[((size_t)t*BSZ + b)*HID + j] + sa0[bi] * g_enc0W[b*HID + j];
                g_cbf[b*HID + j] = __float2bfloat16(v > 0.0f ? v : 0.0f);
            }
        }
        gridbarN(gen, NB2);

        // ---- P2: both gate GEMMs + block-local fuse (all 32 blocks) ----
        for (int s = tid; s < 896; s += TB2)
            *(uint4*)dec_dst(s, sbuf) = *(const uint4*)dec_src(s, nc0, 0);
        __syncthreads();

        wmma::fragment<wmma::accumulator,16,16,16,float> fc0, fc1;
        wmma::fill_fragment(fc0, 0.0f);
        wmma::fill_fragment(fc1, 0.0f);

        for (int kc = 0; kc < 16; kc++) {
            uint4 r0, r1, r2; bool h2v = false;
            if (kc < 15) {
                int k0n = (kc + 1) * 32;
                r0 = *(const uint4*)dec_src(tid, nc0, k0n);
                r1 = *(const uint4*)dec_src(tid + TB2, nc0, k0n);
                if (tid + 2*TB2 < 896) { h2v = true; r2 = *(const uint4*)dec_src(tid + 2*TB2, nc0, k0n); }
            }
            char* cbuf = sbuf + (kc & 1) * 17920;
            __nv_bfloat16* cAc = (__nv_bfloat16*)cbuf;
            __nv_bfloat16* cAh = (__nv_bfloat16*)(cbuf + 5120);
            __nv_bfloat16* cB  = (__nv_bfloat16*)(cbuf + 10240);
            for (int kk = 0; kk < 32; kk += 16) {
                wmma::fragment<wmma::matrix_a,16,16,16,__nv_bfloat16,wmma::row_major> fac, fah;
                wmma::fragment<wmma::matrix_b,16,16,16,__nv_bfloat16,wmma::col_major> fbi, fbh;
                wmma::load_matrix_sync(fac, cAc + (rt*16)*40 + kk, 40);
                wmma::load_matrix_sync(fah, cAh + (rt*16)*40 + kk, 40);
                wmma::load_matrix_sync(fbi, cB + (gate*16)*40 + kk, 40);
                wmma::load_matrix_sync(fbh, cB + (48 + gate*16)*40 + kk, 40);
                wmma::mma_sync(fc0, fac, fbi, fc0);
                wmma::mma_sync(fc1, fah, fbh, fc1);
            }
            if (kc < 15) {
                char* nbuf = sbuf + ((kc + 1) & 1) * 17920;
                *(uint4*)dec_dst(tid, nbuf) = r0;
                *(uint4*)dec_dst(tid + TB2, nbuf) = r1;
                if (h2v) *(uint4*)dec_dst(tid + 2*TB2, nbuf) = r2;
            }
            __syncthreads();
        }

        float* sC = (float*)sbuf;   // 64 x 100 f32 (staging dead after final sync)
        wmma::store_matrix_sync(sC + (rt*16)*100 + gate*16,      fc0, 100, wmma::mem_row_major);
        wmma::store_matrix_sync(sC + (rt*16)*100 + 48 + gate*16, fc1, 100, wmma::mem_row_major);
        __syncthreads();

        for (int idx = tid; idx < 1024; idx += TB2) {
            int b = idx >> 4, l = idx & 15;
            int j = nc0 + l;
            float ir  = sC[b*100 + l];
            float iz  = sC[b*100 + 16 + l];
            float inn = sC[b*100 + 32 + l];
            float hr  = sC[b*100 + 48 + l] + bhh[j];
            float hz  = sC[b*100 + 64 + l] + bhh[j+512];
            float hn  = sC[b*100 + 80 + l] + bhh[j+1024];
            float r = sigmf(ir + bih[j]      + hr);
            float z = sigmf(iz + bih[j+512]  + hz);
            float n = tanhf(inn + bih[j+1024] + r * hn);
            float hp = g_h[b*HID + j];
            float h2 = (1.0f - z)*n + z*hp;
            g_h[b*HID + j] = h2;
            g_hbf[b*HID + j] = __float2bfloat16(h2);
            g_H2bf[(size_t)t*BSZ*HID + b*HID + j] = __float2bfloat16(h2);
        }
        gridbarN(gen, NB2);
    }
}

// ---------------- final logsumexp combine + deterministic loss ----------------
__global__ void k_reduce()
{
    __shared__ float sred[256];
    int m = blockIdx.x * 256 + threadIdx.x;   // 25*256 = 6400 exactly
    const float* pm = g_pm + (size_t)m * NCB;
    const float* ps = g_ps + (size_t)m * NCB;
    float M = pm[0];
    for (int j = 1; j < NCB; j++) M = fmaxf(M, pm[j]);
    float S = 0.0f;
    for (int j = 0; j < NCB; j++) S += ps[j] * expf(pm[j] - M);
    float contrib = (M + logf(S) - g_tgtlog[m]) * (1.0f / 64.0f);
    sred[threadIdx.x] = contrib;
    __syncthreads();
    for (int off = 128; off > 0; off >>= 1) {
        if (threadIdx.x < off) sred[threadIdx.x] += sred[threadIdx.x + off];
        __syncthreads();
    }
    if (threadIdx.x == 0) g_lossp[blockIdx.x] = sred[0];
}

__global__ void k_final(float* __restrict__ out)
{
    float s = 0.0f;
    for (int i = 0; i < 25; i++) s += g_lossp[i];
    out[0] = s;
}

// ---------------- host launcher ----------------
extern "C" void kernel_launch(void* const* d_in, const int* in_sizes, int n_in,
                              void* d_out, int out_size)
{
    const float* emb     = (const float*)d_in[0];
    const float* enc_Wih = (const float*)d_in[1];
    const float* enc_Whh = (const float*)d_in[2];
    const float* enc_bih = (const float*)d_in[3];
    const float* enc_bhh = (const float*)d_in[4];
    const float* attn_W  = (const float*)d_in[5];
    const float* attn_b  = (const float*)d_in[6];
    const float* comb_W  = (const float*)d_in[7];
    const float* comb_b  = (const float*)d_in[8];
    const float* dec_Wih = (const float*)d_in[9];
    const float* dec_Whh = (const float*)d_in[10];
    const float* dec_bih = (const float*)d_in[11];
    const float* dec_bhh = (const float*)d_in[12];
    const float* out_W   = (const float*)d_in[13];
    const float* out_b   = (const float*)d_in[14];
    const int*   in_tok  = (const int*)d_in[15];
    const int*   tgt     = (const int*)d_in[16];

    float *p_attnx, *p_combx, *p_enc0, *p_enc0W, *p_encGx;
    int *p_dectok;
    __nv_bfloat16 *p_embbf, *p_Wobf, *p_Wihbf, *p_H2bf;
    cudaGetSymbolAddress((void**)&p_encGx, g_encGx);
    cudaGetSymbolAddress((void**)&p_attnx, g_attnx);
    cudaGetSymbolAddress((void**)&p_combx, g_combx);
    cudaGetSymbolAddress((void**)&p_enc0,  g_enc0);
    cudaGetSymbolAddress((void**)&p_enc0W, g_enc0W);
    cudaGetSymbolAddress((void**)&p_dectok, g_dectok);
    cudaGetSymbolAddress((void**)&p_embbf, g_embbf);
    cudaGetSymbolAddress((void**)&p_Wobf,  g_Wobf);
    cudaGetSymbolAddress((void**)&p_Wihbf, g_Wihbf);
    cudaGetSymbolAddress((void**)&p_H2bf,  g_H2bf);

    k_init<<<128, 256>>>(tgt);
    k_tobfW<<<4*768, 256>>>(enc_Wih, enc_Whh, dec_Wih, dec_Whh);
    k_tobf<<<(VOC*HID)/1024, 256>>>(emb,   p_embbf, VOC*HID);
    k_tobf<<<(VOC*HID)/1024, 256>>>(out_W, p_Wobf,  VOC*HID);

    // phase A
    k_sgemm128<true><<<dim3(4, 50), 256>>>(emb, p_dectok, attn_W, 1024, attn_b, p_attnx, MROWS, LMAX, HID);
    k_wgemm<0><<<dim3(24, 200), 256>>>(p_embbf, in_tok, p_Wihbf,
                                       (const float*)0, p_encGx, G3,
                                       (const int*)0, G3);
    k_sgemm128<true><<<dim3(4, 50), 256>>>(emb, p_dectok, comb_W, 1024, comb_b, p_combx, MROWS, HID, HID);

    // phase B1: persistent encoder
    k_encoder<<<NB2, TB2>>>(enc_bih, enc_bhh);

    // enc0W = enc0 @ comb_W[:, H:]^T
    k_sgemm128<false><<<dim3(4, 1), 256>>>(p_enc0, (const int*)0, comb_W + 512, 1024,
                                           (const float*)0, p_enc0W, BSZ, HID, HID);

    // phase B2: persistent decoder
    k_decoder<<<NB2, TB2>>>(attn_W, dec_bih, dec_bhh);

    // phase C: projection + fused logsumexp partials
    k_wgemm<1><<<dim3(NCB, 50), 256>>>(p_H2bf, (const int*)0, p_Wobf, out_b,
                                       (float*)0, 0, tgt, VOC);
    k_reduce<<<25, 256>>>();
    k_final<<<1, 1>>>((float*)d_out);
}

// round 11
// speedup vs baseline: 1.6494x; 1.6494x over previous
#include <cuda_runtime.h>
#include <cuda_bf16.h>
#include <mma.h>
#include <math.h>

using namespace nvcuda;

// ---------------- problem constants ----------------
#define BSZ   64
#define HID   512
#define G3    1536
#define LEN   400
#define TOUT  100
#define VOC   50000
#define LMAX  400
#define MROWS (TOUT*BSZ)
#define NCB   391           // phase-C column blocks: ceil(50000/128)
#define NBLK  148
#define KDIM  512

// ---------------- device scratch ----------------
__device__ float g_encGx[(size_t)LEN*BSZ*G3];
__device__ float g_attnx[(size_t)TOUT*BSZ*LMAX];
__device__ float g_combx[(size_t)TOUT*BSZ*HID];
__device__ int   g_dectok[TOUT*BSZ];
__device__ float g_h[BSZ*HID];
__device__ __nv_bfloat16 g_hbf[BSZ*HID];
__device__ __nv_bfloat16 g_cbf[BSZ*HID];
__device__ float g_enc0[BSZ*HID];
__device__ float g_enc0W[BSZ*HID];
__device__ float g_part[4*BSZ*G3];
__device__ float g_a0[BSZ];
__device__ __nv_bfloat16 g_H2bf[(size_t)MROWS*HID];
__device__ __nv_bfloat16 g_embbf[(size_t)VOC*HID];
__device__ __nv_bfloat16 g_Wobf[(size_t)VOC*HID];
__device__ __nv_bfloat16 g_Wihbf[(size_t)G3*HID];
__device__ __nv_bfloat16 g_Whhbf[(size_t)G3*HID];
__device__ __nv_bfloat16 g_dWihbf[(size_t)G3*HID];
__device__ __nv_bfloat16 g_dWhhbf[(size_t)G3*HID];
__device__ float g_pm[(size_t)MROWS*NCB];
__device__ float g_ps[(size_t)MROWS*NCB];
__device__ float g_tgtlog[MROWS];
__device__ float g_lossp[32];

__device__ unsigned g_barcnt;
__device__ unsigned g_bargen;

__device__ __forceinline__ float sigmf(float x) { return 1.0f / (1.0f + expf(-x)); }

__device__ __forceinline__ void gridbar(unsigned &gen)
{
    __syncthreads();
    if (threadIdx.x == 0) {
        __threadfence();
        unsigned prev = atomicAdd(&g_barcnt, 1u);
        if (prev == NBLK - 1u) {
            atomicExch(&g_barcnt, 0u);
            __threadfence();
            atomicAdd(&g_bargen, 1u);
        } else {
            while (atomicAdd(&g_bargen, 0u) == gen) __nanosleep(64);
        }
        gen++;
    }
    __syncthreads();
}

// ---------------- fp32 -> bf16 conversion ----------------
__global__ void k_tobf(const float* __restrict__ s, __nv_bfloat16* __restrict__ d, int n)
{
    int i = (blockIdx.x * 256 + threadIdx.x) << 2;
    if (i < n) {
        float4 v = *(const float4*)(s + i);
        *(__nv_bfloat162*)(d + i)     = __floats2bfloat162_rn(v.x, v.y);
        *(__nv_bfloat162*)(d + i + 2) = __floats2bfloat162_rn(v.z, v.w);
    }
}

__global__ void k_init(const int* __restrict__ tgt)
{
    int i = blockIdx.x * 256 + threadIdx.x;
    if (i < BSZ*HID) {
        g_h[i] = 0.0f;
        g_hbf[i] = __float2bfloat16(0.0f);
    }
    if (i < TOUT*BSZ) {
        int t = i / BSZ, b = i % BSZ;
        g_dectok[i] = (t == 0) ? 1 : tgt[(t-1)*BSZ + b];
    }
}

// ================= bf16 WMMA GEMM, 128(M) x 128(N) block, K=512, double-buffered =================
// MODE 0: A row m = Abf[gidx[m]] (token gather), store raw C to Cout (no bias).
// MODE 1: A row m = Abf[m], fused bias + streaming logsumexp epilogue (two 64-col halves).
template<int MODE>
__global__ void __launch_bounds__(256)
k_wgemm(const __nv_bfloat16* __restrict__ Abf,
        const int* __restrict__ gidx,
        const __nv_bfloat16* __restrict__ Bbf,
        const float* __restrict__ bias,
        float* __restrict__ Cout, int ldC,
        const int* __restrict__ tgt,
        int Ncols)
{
    // 40960B: double-buffered staging (2 x (10240 A + 10240 B)); epilogue reuses as sC 128x72 f32
    __shared__ __align__(16) char sbuf[40960];
    float* sC = (float*)sbuf;

    const int tid  = threadIdx.x;
    const int warp = tid >> 5;
    const int rt = warp & 3;         // row tile of 32
    const int cn = warp >> 2;        // col half of 64
    const int bm = blockIdx.y * 128;
    const int bn = blockIdx.x * 128;

    const int cr = tid >> 2;         // 0..63
    const int q8 = (tid & 3) << 3;   // 0,8,16,24

    size_t ga0, ga1;
    if (MODE == 0) {
        ga0 = (size_t)gidx[bm + cr]      * KDIM + q8;
        ga1 = (size_t)gidx[bm + cr + 64] * KDIM + q8;
    } else {
        ga0 = (size_t)(bm + cr)      * KDIM + q8;
        ga1 = (size_t)(bm + cr + 64) * KDIM + q8;
    }
    int nb0 = bn + cr;      if (nb0 >= Ncols) nb0 = Ncols - 1;
    int nb1 = bn + cr + 64; if (nb1 >= Ncols) nb1 = Ncols - 1;
    size_t gb0 = (size_t)nb0 * KDIM + q8;
    size_t gb1 = (size_t)nb1 * KDIM + q8;

    const int sa0 = cr*40 + q8;
    const int sa1 = sa0 + 64*40;

    __nv_bfloat16* bufA[2] = { (__nv_bfloat16*)sbuf, (__nv_bfloat16*)(sbuf + 20480) };
    __nv_bfloat16* bufB[2] = { (__nv_bfloat16*)(sbuf + 10240), (__nv_bfloat16*)(sbuf + 30720) };

    uint4 rA0 = *(const uint4*)(Abf + ga0);
    uint4 rA1 = *(const uint4*)(Abf + ga1);
    uint4 rB0 = *(const uint4*)(Bbf + gb0);
    uint4 rB1 = *(const uint4*)(Bbf + gb1);
    *(uint4*)(bufA[0] + sa0) = rA0;
    *(uint4*)(bufA[0] + sa1) = rA1;
    *(uint4*)(bufB[0] + sa0) = rB0;
    *(uint4*)(bufB[0] + sa1) = rB1;
    __syncthreads();

    wmma::fragment<wmma::accumulator, 16, 16, 16, float> fc[2][4];
    for (int mi = 0; mi < 2; mi++)
        for (int ni = 0; ni < 4; ni++)
            wmma::fill_fragment(fc[mi][ni], 0.0f);

    for (int it = 0; it < 16; it++) {
        if (it < 15) {
            int kg = (it + 1) * 32;
            rA0 = *(const uint4*)(Abf + ga0 + kg);
            rA1 = *(const uint4*)(Abf + ga1 + kg);
            rB0 = *(const uint4*)(Bbf + gb0 + kg);
            rB1 = *(const uint4*)(Bbf + gb1 + kg);
        }
        __nv_bfloat16* cA = bufA[it & 1];
        __nv_bfloat16* cB = bufB[it & 1];
        for (int kk = 0; kk < 32; kk += 16) {
            wmma::fragment<wmma::matrix_a, 16, 16, 16, __nv_bfloat16, wmma::row_major> fa[2];
            wmma::fragment<wmma::matrix_b, 16, 16, 16, __nv_bfloat16, wmma::col_major> fb[4];
            wmma::load_matrix_sync(fa[0], cA + (rt*32     )*40 + kk, 40);
            wmma::load_matrix_sync(fa[1], cA + (rt*32 + 16)*40 + kk, 40);
            for (int ni = 0; ni < 4; ni++)
                wmma::load_matrix_sync(fb[ni], cB + (cn*64 + ni*16)*40 + kk, 40);
            for (int mi = 0; mi < 2; mi++)
                for (int ni = 0; ni < 4; ni++)
                    wmma::mma_sync(fc[mi][ni], fa[mi], fb[ni], fc[mi][ni]);
        }
        if (it < 15) {
            __nv_bfloat16* nA = bufA[(it + 1) & 1];
            __nv_bfloat16* nB = bufB[(it + 1) & 1];
            *(uint4*)(nA + sa0) = rA0;
            *(uint4*)(nA + sa1) = rA1;
            *(uint4*)(nB + sa0) = rB0;
            *(uint4*)(nB + sa1) = rB1;
        }
        __syncthreads();
    }

    if (MODE == 0) {
        for (int mi = 0; mi < 2; mi++)
            for (int ni = 0; ni < 4; ni++) {
                size_t row = bm + rt*32 + mi*16;
                int col = bn + cn*64 + ni*16;
                wmma::store_matrix_sync(Cout + row * (size_t)ldC + col,
                                        fc[mi][ni], ldC, wmma::mem_row_major);
            }
    } else {
        const int r  = tid >> 1;
        const int hf = tid & 1;
        const int rg = bm + r;
        const int tv = tgt[rg];
        float Mrun = -1e30f, Srun = 0.0f;

        for (int h = 0; h < 2; h++) {
            if (cn == h) {
                for (int mi = 0; mi < 2; mi++)
                    for (int ni = 0; ni < 4; ni++)
                        wmma::store_matrix_sync(sC + (rt*32 + mi*16)*72 + ni*16,
                                                fc[mi][ni], 72, wmma::mem_row_major);
            }
            __syncthreads();

            float* crow = sC + r*72 + hf*32;
            int cbase = bn + h*64 + hf*32;
            float mx = -1e30f;
            for (int c = 0; c < 32; c++) {
                int gc = cbase + c;
                float v = (gc < Ncols) ? (crow[c] + bias[gc]) : -1e30f;
                crow[c] = v;
                mx = fmaxf(mx, v);
            }
            float s = 0.0f;
            for (int c = 0; c < 32; c++) s += expf(crow[c] - mx);

            float mo = __shfl_xor_sync(0xffffffffu, mx, 1);
            float so = __shfl_xor_sync(0xffffffffu, s,  1);
            float M2 = fmaxf(mx, mo);
            float S2 = s * expf(mx - M2) + so * expf(mo - M2);

            int lc = tv - cbase;
            if (lc >= 0 && lc < 32) g_tgtlog[rg] = crow[lc];

            float nm = fmaxf(Mrun, M2);
            Srun = Srun * expf(Mrun - nm) + S2 * expf(M2 - nm);
            Mrun = nm;
            __syncthreads();
        }
        if (hf == 0) {
            g_pm[(size_t)rg * NCB + blockIdx.x] = Mrun;
            g_ps[(size_t)rg * NCB + blockIdx.x] = Srun;
        }
    }
}

// ---------------- generic fp32 SGEMM (small phase-A ops) ----------------
template<bool GATHER>
__global__ void __launch_bounds__(256)
k_sgemm128(const float* __restrict__ A,
           const int*  __restrict__ gidx,
           const float* __restrict__ Bw, int ldb,
           const float* __restrict__ bias,
           float* __restrict__ C,
           int M, int N, int K)
{
    __shared__ __align__(16) float sA[16][128];
    __shared__ __align__(16) float sB[16][128];
    const int tid = threadIdx.x;
    const int bm = blockIdx.y * 128;
    const int bn = blockIdx.x * 128;
    const int tx = tid & 15;
    const int ty = tid >> 4;
    const int lr = tid >> 2;
    const int lk = (tid & 3) << 2;

    int m0 = bm + lr, m1 = m0 + 64;
    const bool mv0 = m0 < M, mv1 = m1 < M;
    size_t ar0, ar1;
    if (GATHER) {
        ar0 = (size_t)(mv0 ? gidx[m0] : gidx[0]) * (size_t)K;
        ar1 = (size_t)(mv1 ? gidx[m1] : gidx[0]) * (size_t)K;
    } else {
        ar0 = (size_t)(mv0 ? m0 : 0) * (size_t)K;
        ar1 = (size_t)(mv1 ? m1 : 0) * (size_t)K;
    }
    int n0 = bn + lr, n1 = n0 + 64;
    size_t br0 = (size_t)(n0 < N ? n0 : 0) * (size_t)ldb;
    size_t br1 = (size_t)(n1 < N ? n1 : 0) * (size_t)ldb;

    float acc[8][8];
#pragma unroll
    for (int i = 0; i < 8; i++)
#pragma unroll
        for (int j = 0; j < 8; j++) acc[i][j] = 0.0f;

    for (int kb = 0; kb < K; kb += 16) {
        float4 a0 = *(const float4*)(A  + ar0 + kb + lk);
        float4 a1 = *(const float4*)(A  + ar1 + kb + lk);
        float4 b0 = *(const float4*)(Bw + br0 + kb + lk);
        float4 b1 = *(const float4*)(Bw + br1 + kb + lk);
        __syncthreads();
        sA[lk+0][lr] = a0.x; sA[lk+1][lr] = a0.y; sA[lk+2][lr] = a0.z; sA[lk+3][lr] = a0.w;
        sA[lk+0][lr+64] = a1.x; sA[lk+1][lr+64] = a1.y; sA[lk+2][lr+64] = a1.z; sA[lk+3][lr+64] = a1.w;
        sB[lk+0][lr] = b0.x; sB[lk+1][lr] = b0.y; sB[lk+2][lr] = b0.z; sB[lk+3][lr] = b0.w;
        sB[lk+0][lr+64] = b1.x; sB[lk+1][lr+64] = b1.y; sB[lk+2][lr+64] = b1.z; sB[lk+3][lr+64] = b1.w;
        __syncthreads();
#pragma unroll
        for (int k = 0; k < 16; k++) {
            float4 pa0 = *(const float4*)(&sA[k][ty*8]);
            float4 pa1 = *(const float4*)(&sA[k][ty*8+4]);
            float4 pb0 = *(const float4*)(&sB[k][tx*8]);
            float4 pb1 = *(const float4*)(&sB[k][tx*8+4]);
            float av[8] = {pa0.x, pa0.y, pa0.z, pa0.w, pa1.x, pa1.y, pa1.z, pa1.w};
            float bv[8] = {pb0.x, pb0.y, pb0.z, pb0.w, pb1.x, pb1.y, pb1.z, pb1.w};
#pragma unroll
            for (int i = 0; i < 8; i++)
#pragma unroll
                for (int j = 0; j < 8; j++)
                    acc[i][j] += av[i] * bv[j];
        }
    }

#pragma unroll
    for (int i = 0; i < 8; i++) {
        int m = bm + ty*8 + i;
        if (m < M) {
            float* crow = C + (size_t)m * (size_t)N;
#pragma unroll
            for (int j = 0; j < 8; j++) {
                int n = bn + tx*8 + j;
                if (n < N) crow[n] = acc[i][j] + (bias ? bias[n] : 0.0f);
            }
        }
    }
}

// ---------------- per-task 64x64 WMMA step-GEMM, K=256, double-buffered ----------------
__device__ __forceinline__ void step_wmma_task(
    const __nv_bfloat16* __restrict__ A, const __nv_bfloat16* __restrict__ B,
    int bn, int kbase, float* __restrict__ Cp, char* sbuf)
{
    const int tid  = threadIdx.x;
    const int warp = tid >> 5;
    const int wm = warp >> 2;        // 0..1
    const int wn = warp & 3;         // 0..3
    const int cr = tid >> 2;         // 0..63
    const int q8 = (tid & 3) << 3;

    size_t aoff = (size_t)cr * HID + kbase + q8;
    size_t boff = (size_t)(bn + cr) * HID + kbase + q8;
    const int si = cr*40 + q8;

    __nv_bfloat16* bufA[2] = { (__nv_bfloat16*)sbuf, (__nv_bfloat16*)(sbuf + 10240) };
    __nv_bfloat16* bufB[2] = { (__nv_bfloat16*)(sbuf + 5120), (__nv_bfloat16*)(sbuf + 15360) };

    uint4 ra = *(const uint4*)(A + aoff);
    uint4 rb = *(const uint4*)(B + boff);
    *(uint4*)(bufA[0] + si) = ra;
    *(uint4*)(bufB[0] + si) = rb;
    __syncthreads();

    wmma::fragment<wmma::accumulator,16,16,16,float> fc0, fc1;
    wmma::fill_fragment(fc0, 0.0f);
    wmma::fill_fragment(fc1, 0.0f);

    for (int it = 0; it < 8; it++) {
        if (it < 7) {
            int kg = (it + 1) * 32;
            ra = *(const uint4*)(A + aoff + kg);
            rb = *(const uint4*)(B + boff + kg);
        }
        __nv_bfloat16* cA = bufA[it & 1];
        __nv_bfloat16* cB = bufB[it & 1];
        for (int kk = 0; kk < 32; kk += 16) {
            wmma::fragment<wmma::matrix_a,16,16,16,__nv_bfloat16,wmma::row_major> fa0, fa1;
            wmma::fragment<wmma::matrix_b,16,16,16,__nv_bfloat16,wmma::col_major> fb;
            wmma::load_matrix_sync(fa0, cA + (wm*32     )*40 + kk, 40);
            wmma::load_matrix_sync(fa1, cA + (wm*32 + 16)*40 + kk, 40);
            wmma::load_matrix_sync(fb,  cB + (wn*16     )*40 + kk, 40);
            wmma::mma_sync(fc0, fa0, fb, fc0);
            wmma::mma_sync(fc1, fa1, fb, fc1);
        }
        if (it < 7) {
            __nv_bfloat16* nA = bufA[(it + 1) & 1];
            __nv_bfloat16* nB = bufB[(it + 1) & 1];
            *(uint4*)(nA + si) = ra;
            *(uint4*)(nB + si) = rb;
        }
        __syncthreads();
    }
    wmma::store_matrix_sync(Cp + (size_t)(wm*32     )*G3 + bn + wn*16, fc0, G3, wmma::mem_row_major);
    wmma::store_matrix_sync(Cp + (size_t)(wm*32 + 16)*G3 + bn + wn*16, fc1, G3, wmma::mem_row_major);
}

// ---------------- persistent encoder (148 blocks, 2 barriers/step) ----------------
__global__ void __launch_bounds__(256)
k_encoder(const float* __restrict__ bih, const float* __restrict__ bhh)
{
    __shared__ __align__(16) char sbuf[20480];
    unsigned gen = 0;
    if (threadIdx.x == 0) gen = atomicAdd(&g_bargen, 0u);
    const int blk = blockIdx.x;

    for (int t = 0; t < LEN; t++) {
        if (blk < 48) {
            int ks = blk / 24, nb = blk % 24;
            step_wmma_task(g_hbf, g_Whhbf, nb*64, ks*256, g_part + (size_t)ks*BSZ*G3, sbuf);
        }
        gridbar(gen);
        if (blk < 128) {
            int idx = blk*256 + threadIdx.x;
            int b = idx >> 9, j = idx & 511;
            int base = b * G3;
            float hr = bhh[j], hz = bhh[j+512], hn = bhh[j+1024];
#pragma unroll
            for (int s = 0; s < 2; s++) {
                const float* p = g_part + (size_t)s * BSZ * G3 + base;
                hr += p[j]; hz += p[j+512]; hn += p[j+1024];
            }
            const float* gx = g_encGx + ((size_t)t*BSZ + b) * G3;
            float r = sigmf(gx[j] + bih[j] + hr);
            float z = sigmf(gx[j+512] + bih[j+512] + hz);
            float n = tanhf(gx[j+1024] + bih[j+1024] + r * hn);
            float hp = g_h[idx];
            float h2 = (1.0f - z) * n + z * hp;
            g_h[idx] = h2;
            g_hbf[idx] = __float2bfloat16(h2);
            if (t == 0) g_enc0[idx] = h2;
        }
        gridbar(gen);
    }
}

// ---------------- persistent decoder (148 blocks, 4 barriers/step) ----------------
__global__ void __launch_bounds__(256)
k_decoder(const float* __restrict__ attn_W,
          const float* __restrict__ bih, const float* __restrict__ bhh)
{
    __shared__ __align__(16) char sbuf[20480];
    float* sm = (float*)sbuf;
    unsigned gen = 0;
    if (threadIdx.x == 0) gen = atomicAdd(&g_bargen, 0u);
    const int blk = blockIdx.x;
    const int tid = threadIdx.x;

    for (int t = 0; t < TOUT; t++) {
        if (blk < 64) {
            const int b = blk;
            float* sh = sm;
            float* slg = sm + 512;
            float* sred = sm + 912;
            sh[tid]       = g_h[b*HID + tid];
            sh[tid + 256] = g_h[b*HID + tid + 256];
            __syncthreads();
            const float4* h4 = (const float4*)sh;
            for (int l = tid; l < LMAX; l += 256) {
                const float4* w4 = (const float4*)(attn_W + (size_t)l*1024 + 512);
                float s = 0.0f;
#pragma unroll 4
                for (int k = 0; k < 128; k++) {
                    float4 w = w4[k], h = h4[k];
                    s += w.x*h.x + w.y*h.y + w.z*h.z + w.w*h.w;
                }
                slg[l] = g_attnx[((size_t)t*BSZ + b)*LMAX + l] + s;
            }
            __syncthreads();
            float lm = -1e30f;
            for (int l = tid; l < LMAX; l += 256) lm = fmaxf(lm, slg[l]);
            sred[tid] = lm; __syncthreads();
            for (int off = 128; off > 0; off >>= 1) {
                if (tid < off) sred[tid] = fmaxf(sred[tid], sred[tid+off]);
                __syncthreads();
            }
            float mx = sred[0];
            __syncthreads();
            float ls = 0.0f;
            for (int l = tid; l < LMAX; l += 256) ls += expf(slg[l] - mx);
            sred[tid] = ls; __syncthreads();
            for (int off = 128; off > 0; off >>= 1) {
                if (tid < off) sred[tid] += sred[tid+off];
                __syncthreads();
            }
            if (tid == 0) g_a0[b] = expf(slg[0] - mx) / sred[0];
        }
        gridbar(gen);
        if (blk < 128) {
            int idx = blk*256 + tid;
            int b = idx >> 9, j = idx & 511;
            float v = g_combx[((size_t)t*BSZ + b)*HID + j] + g_a0[b] * g_enc0W[idx];
            g_cbf[idx] = __float2bfloat16(v > 0.0f ? v : 0.0f);
        }
        gridbar(gen);
        if (blk < 96) {
            int group = blk / 48, rem = blk % 48;
            int ks = rem / 24, nb = rem % 24;
            const __nv_bfloat16* A  = group ? g_hbf : g_cbf;
            const __nv_bfloat16* Bm = group ? g_dWhhbf : g_dWihbf;
            step_wmma_task(A, Bm, nb*64, ks*256,
                           g_part + (size_t)(group*2 + ks)*BSZ*G3, sbuf);
        }
        gridbar(gen);
        if (blk < 128) {
            int idx = blk*256 + tid;
            int b = idx >> 9, j = idx & 511;
            int base = b * G3;
            float ir = bih[j], iz = bih[j+512], in = bih[j+1024];
            float hr = bhh[j], hz = bhh[j+512], hn = bhh[j+1024];
#pragma unroll
            for (int s = 0; s < 2; s++) {
                const float* pi = g_part + (size_t)s * BSZ * G3 + base;
                const float* ph = g_part + (size_t)(s+2) * BSZ * G3 + base;
                ir += pi[j]; iz += pi[j+512]; in += pi[j+1024];
                hr += ph[j]; hz += ph[j+512]; hn += ph[j+1024];
            }
            float r = sigmf(ir + hr);
            float z = sigmf(iz + hz);
            float n = tanhf(in + r * hn);
            float hp = g_h[idx];
            float h2 = (1.0f - z) * n + z * hp;
            g_h[idx] = h2;
            g_hbf[idx] = __float2bfloat16(h2);
            g_H2bf[(size_t)t*BSZ*HID + idx] = __float2bfloat16(h2);
        }
        gridbar(gen);
    }
}

// ---------------- final logsumexp combine + deterministic loss ----------------
__global__ void k_reduce()
{
    __shared__ float sred[256];
    int m = blockIdx.x * 256 + threadIdx.x;
    const float* pm = g_pm + (size_t)m * NCB;
    const float* ps = g_ps + (size_t)m * NCB;
    float M = pm[0];
    for (int j = 1; j < NCB; j++) M = fmaxf(M, pm[j]);
    float S = 0.0f;
    for (int j = 0; j < NCB; j++) S += ps[j] * expf(pm[j] - M);
    float contrib = (M + logf(S) - g_tgtlog[m]) * (1.0f / 64.0f);
    sred[threadIdx.x] = contrib;
    __syncthreads();
    for (int off = 128; off > 0; off >>= 1) {
        if (threadIdx.x < off) sred[threadIdx.x] += sred[threadIdx.x + off];
        __syncthreads();
    }
    if (threadIdx.x == 0) g_lossp[blockIdx.x] = sred[0];
}

__global__ void k_final(float* __restrict__ out)
{
    float s = 0.0f;
    for (int i = 0; i < 25; i++) s += g_lossp[i];
    out[0] = s;
}

// ---------------- host launcher ----------------
extern "C" void kernel_launch(void* const* d_in, const int* in_sizes, int n_in,
                              void* d_out, int out_size)
{
    const float* emb     = (const float*)d_in[0];
    const float* enc_Wih = (const float*)d_in[1];
    const float* enc_Whh = (const float*)d_in[2];
    const float* enc_bih = (const float*)d_in[3];
    const float* enc_bhh = (const float*)d_in[4];
    const float* attn_W  = (const float*)d_in[5];
    const float* attn_b  = (const float*)d_in[6];
    const float* comb_W  = (const float*)d_in[7];
    const float* comb_b  = (const float*)d_in[8];
    const float* dec_Wih = (const float*)d_in[9];
    const float* dec_Whh = (const float*)d_in[10];
    const float* dec_bih = (const float*)d_in[11];
    const float* dec_bhh = (const float*)d_in[12];
    const float* out_W   = (const float*)d_in[13];
    const float* out_b   = (const float*)d_in[14];
    const int*   in_tok  = (const int*)d_in[15];
    const int*   tgt     = (const int*)d_in[16];

    float *p_attnx, *p_combx, *p_enc0, *p_enc0W, *p_encGx;
    int *p_dectok;
    __nv_bfloat16 *p_embbf, *p_Wobf, *p_Wihbf, *p_Whhbf, *p_dWihbf, *p_dWhhbf, *p_H2bf;
    cudaGetSymbolAddress((void**)&p_encGx, g_encGx);
    cudaGetSymbolAddress((void**)&p_attnx, g_attnx);
    cudaGetSymbolAddress((void**)&p_combx, g_combx);
    cudaGetSymbolAddress((void**)&p_enc0,  g_enc0);
    cudaGetSymbolAddress((void**)&p_enc0W, g_enc0W);
    cudaGetSymbolAddress((void**)&p_dectok, g_dectok);
    cudaGetSymbolAddress((void**)&p_embbf, g_embbf);
    cudaGetSymbolAddress((void**)&p_Wobf,  g_Wobf);
    cudaGetSymbolAddress((void**)&p_Wihbf, g_Wihbf);
    cudaGetSymbolAddress((void**)&p_Whhbf, g_Whhbf);
    cudaGetSymbolAddress((void**)&p_dWihbf, g_dWihbf);
    cudaGetSymbolAddress((void**)&p_dWhhbf, g_dWhhbf);
    cudaGetSymbolAddress((void**)&p_H2bf,  g_H2bf);

    k_init<<<128, 256>>>(tgt);
    k_tobf<<<(VOC*HID)/1024, 256>>>(emb,     p_embbf, VOC*HID);
    k_tobf<<<(VOC*HID)/1024, 256>>>(out_W,   p_Wobf,  VOC*HID);
    k_tobf<<<(G3*HID)/1024,  256>>>(enc_Wih, p_Wihbf, G3*HID);
    k_tobf<<<(G3*HID)/1024,  256>>>(enc_Whh, p_Whhbf, G3*HID);
    k_tobf<<<(G3*HID)/1024,  256>>>(dec_Wih, p_dWihbf, G3*HID);
    k_tobf<<<(G3*HID)/1024,  256>>>(dec_Whh, p_dWhhbf, G3*HID);

    // phase A: encGx via WMMA (128x128 tiles), small fp32 GEMMs for decoder x-parts
    k_wgemm<0><<<dim3(12, 200), 256>>>(p_embbf, in_tok, p_Wihbf,
                                       (const float*)0, p_encGx, G3,
                                       (const int*)0, G3);
    k_sgemm128<true><<<dim3(4, 50), 256>>>(emb, p_dectok, attn_W, 1024, attn_b, p_attnx, MROWS, LMAX, HID);
    k_sgemm128<true><<<dim3(4, 50), 256>>>(emb, p_dectok, comb_W, 1024, comb_b, p_combx, MROWS, HID, HID);

    // phase B1: persistent encoder
    k_encoder<<<NBLK, 256>>>(enc_bih, enc_bhh);

    // enc0W = enc0 @ comb_W[:, H:]^T
    k_sgemm128<false><<<dim3(4, 1), 256>>>(p_enc0, (const int*)0, comb_W + 512, 1024,
                                           (const float*)0, p_enc0W, BSZ, HID, HID);

    // phase B2: persistent decoder
    k_decoder<<<NBLK, 256>>>(attn_W, dec_bih, dec_bhh);

    // phase C: 128x128 WMMA projection with fused logsumexp partials
    k_wgemm<1><<<dim3(NCB, 50), 256>>>(p_H2bf, (const int*)0, p_Wobf, out_b,
                                       (float*)0, 0, tgt, VOC);
    k_reduce<<<25, 256>>>();
    k_final<<<1, 1>>>((float*)d_out);
}